// round 9
// baseline (speedup 1.0000x reference)
#include <cuda_runtime.h>

#define BB 4
#define SS 256
#define DD 512
#define PP 256
#define TI 4    // query rows per score block
#define PH (PP/2)

// Scratch (device globals — no allocation allowed)
__device__ float g_pq [BB*SS*PP];   // [b][i][p]
__device__ float g_pkT[BB*PP*SS];   // [b][p][j]

__device__ __forceinline__ float fast_tanh(float x) {
    float y; asm("tanh.approx.f32 %0, %1;" : "=f"(y) : "f"(x)); return y;
}

// ---------------------------------------------------------------------------
// Phase 1: pq = seq @ W2^T ([b][i][p]); pk = seq @ W1^T (transposed [b][p][j])
// 32x64 tile (M=seq rows, N=p), K-chunk 16, 256 thr, 2x4 microtile,
// double-buffered.  grid (4,32,2) = 256 CTAs -> 2 CTAs/SM.
// ---------------------------------------------------------------------------
__global__ __launch_bounds__(256, 2) void proj_kernel(
    const float* __restrict__ seq,
    const float* __restrict__ W1,
    const float* __restrict__ W2)
{
    __shared__ float As[2][16][36];   // [buf][k][m]  m=32 rows
    __shared__ float Bs[2][16][68];   // [buf][k][n]  n=64 p-cols
    const float* Wm = blockIdx.z ? W1 : W2;
    const int row0 = blockIdx.y * 32;     // seq row
    const int col0 = blockIdx.x * 64;     // p col
    const int tid = threadIdx.x;
    const int tx = tid & 15, ty = tid >> 4;   // tx->4 cols, ty->2 rows
    const int lmA  = tid >> 3;            // 0..31  A row
    const int lkA  = (tid & 7) << 1;      // 0..14  A k (float2)
    const int lmB  = tid >> 2;            // 0..63  B row (p)
    const int lkB  = (tid & 3) << 2;      // 0,4,8,12 B k (float4)

    const float* ap = seq + (row0 + lmA) * DD + lkA;
    const float* wp = Wm  + (col0 + lmB) * DD + lkB;

    {   // prologue chunk 0
        float2 a = *(const float2*)ap;
        float4 w = *(const float4*)wp;
        As[0][lkA+0][lmA] = a.x; As[0][lkA+1][lmA] = a.y;
        Bs[0][lkB+0][lmB] = w.x; Bs[0][lkB+1][lmB] = w.y;
        Bs[0][lkB+2][lmB] = w.z; Bs[0][lkB+3][lmB] = w.w;
    }
    __syncthreads();

    float acc[2][4] = {};
    int buf = 0;

    for (int k0 = 0; k0 < DD; k0 += 16) {
        float2 an; float4 wn;
        const bool has_next = (k0 + 16) < DD;
        if (has_next) {
            an = *(const float2*)(ap + k0 + 16);
            wn = *(const float4*)(wp + k0 + 16);
        }
        #pragma unroll
        for (int k = 0; k < 16; k++) {
            float2 av = *(const float2*)&As[buf][k][ty << 1];
            float4 bv = *(const float4*)&Bs[buf][k][tx << 2];
            float bn[4] = {bv.x, bv.y, bv.z, bv.w};
            #pragma unroll
            for (int j = 0; j < 4; j++) {
                acc[0][j] = fmaf(av.x, bn[j], acc[0][j]);
                acc[1][j] = fmaf(av.y, bn[j], acc[1][j]);
            }
        }
        if (has_next) {
            const int nb = buf ^ 1;
            As[nb][lkA+0][lmA] = an.x; As[nb][lkA+1][lmA] = an.y;
            Bs[nb][lkB+0][lmB] = wn.x; Bs[nb][lkB+1][lmB] = wn.y;
            Bs[nb][lkB+2][lmB] = wn.z; Bs[nb][lkB+3][lmB] = wn.w;
            __syncthreads();
            buf = nb;
        }
    }

    #pragma unroll
    for (int i = 0; i < 2; i++) {
        const int row = row0 + (ty << 1) + i;
        const int col = col0 + (tx << 2);
        if (blockIdx.z == 0) {
            *(float4*)&g_pq[row * PP + col] =
                make_float4(acc[i][0], acc[i][1], acc[i][2], acc[i][3]);
        } else {
            const int b = row >> 8, jj = row & 255;
            #pragma unroll
            for (int j = 0; j < 4; j++)
                g_pkT[(b * PP + col + j) * SS + jj] = acc[i][j];
        }
    }
}

// ---------------------------------------------------------------------------
// Phase 2 (fused): scores (p-split across block halves) + softmax.
// Block = 512 thr: half h = tid>>8 reduces p in [h*128, h*128+128).
// Partials meet in smem; warps 0..3 do softmax and write weights.
// grid = 256 blocks (b x 64 i-tiles).
// ---------------------------------------------------------------------------
__global__ __launch_bounds__(512) void score_kernel(
    const float* __restrict__ mask,
    const float* __restrict__ v,
    float* __restrict__ out_w)
{
    __shared__ float pq_s[2][TI][PH];
    __shared__ float v_s[2][PH];
    __shared__ float sp_s[2][TI][SS];

    const int blk = blockIdx.x;
    const int b  = blk >> 6;                 // 64 i-tiles per batch
    const int i0 = (blk & 63) * TI;
    const int tid = threadIdx.x;
    const int h = tid >> 8;                  // p-half
    const int t = tid & 255;                 // key j
    const int pbase = h * PH;

    if (t < PH) {
        v_s[h][t] = v[pbase + t];
        #pragma unroll
        for (int ii = 0; ii < TI; ii++)
            pq_s[h][ii][t] = g_pq[(b * SS + i0 + ii) * PP + pbase + t];
    }
    __syncthreads();

    float acc[TI];
    #pragma unroll
    for (int ii = 0; ii < TI; ii++) acc[ii] = 0.f;

    const float* pkp = g_pkT + (b * PP + pbase) * SS + t;
    #pragma unroll 4
    for (int p = 0; p < PH; p++) {
        float pk = pkp[p * SS];              // coalesced, L2-resident
        float vv = v_s[h][p];
        #pragma unroll
        for (int ii = 0; ii < TI; ii++)
            acc[ii] = fmaf(vv, fast_tanh(pq_s[h][ii][p] + pk), acc[ii]);
    }
    #pragma unroll
    for (int ii = 0; ii < TI; ii++)
        sp_s[h][ii][t] = acc[ii];
    __syncthreads();

    // softmax: warps 0..3, warp wrp = query row i0+wrp
    if (tid < 128) {
        const int wrp = tid >> 5, lane = tid & 31;
        const float* mrow = mask + b * SS;
        float vals[8];
        float m = -3.4e38f;
        #pragma unroll
        for (int k = 0; k < 8; k++) {
            const int j = lane + 32 * k;
            float s = sp_s[0][wrp][j] + sp_s[1][wrp][j];
            s = (mrow[j] > 0.f) ? s : -1e9f;
            vals[k] = s;
            m = fmaxf(m, s);
        }
        #pragma unroll
        for (int o = 16; o > 0; o >>= 1) m = fmaxf(m, __shfl_xor_sync(0xffffffffu, m, o));
        float sum = 0.f;
        #pragma unroll
        for (int k = 0; k < 8; k++) { vals[k] = __expf(vals[k] - m); sum += vals[k]; }
        #pragma unroll
        for (int o = 16; o > 0; o >>= 1) sum += __shfl_xor_sync(0xffffffffu, sum, o);
        const float qm  = mrow[i0 + wrp];
        const float inv = qm / sum;          // fold query-mask into weights
        float* orow = out_w + (b * SS + i0 + wrp) * SS;
        #pragma unroll
        for (int k = 0; k < 8; k++)
            orow[lane + 32 * k] = vals[k] * inv;
    }
}

// ---------------------------------------------------------------------------
// Phase 3: attn = weights @ seq.  32x64 tile, 256 thr, 2x4 microtile,
// double-buffered.  grid (8,32) = 256 CTAs.
// ---------------------------------------------------------------------------
__global__ __launch_bounds__(256, 2) void av_kernel(
    const float* __restrict__ w,      // [B*S, S]
    const float* __restrict__ seq,    // [B, S, D]
    float* __restrict__ out_attn)     // [B*S, D]
{
    __shared__ float As[2][16][36];   // [buf][k][m]  m=32 query rows
    __shared__ float Bs[2][16][68];   // [buf][k][n]  n=64 d-cols
    const int row0 = blockIdx.y * 32;
    const int col0 = blockIdx.x * 64;
    const int b = row0 >> 8;
    const int tid = threadIdx.x;
    const int tx = tid & 15, ty = tid >> 4;
    const int lmA = tid >> 3;            // 0..31 (A row)
    const int lkA = (tid & 7) << 1;      // A k (float2)
    const int kb  = tid >> 4;            // 0..15 (B k row)
    const int nb  = (tid & 15) << 2;     // B n col (float4)

    const float* ap = w + (row0 + lmA) * SS + lkA;
    const float* sp = seq + b * SS * DD + kb * DD + col0 + nb;

    {
        float2 a = *(const float2*)ap;
        float4 s = *(const float4*)sp;
        As[0][lkA+0][lmA] = a.x; As[0][lkA+1][lmA] = a.y;
        *(float4*)&Bs[0][kb][nb] = s;
    }
    __syncthreads();

    float acc[2][4] = {};
    int buf = 0;

    for (int k0 = 0; k0 < SS; k0 += 16) {
        float2 an; float4 sn;
        const bool has_next = (k0 + 16) < SS;
        if (has_next) {
            an = *(const float2*)(ap + k0 + 16);
            sn = *(const float4*)(sp + (k0 + 16) * DD);
        }
        #pragma unroll
        for (int k = 0; k < 16; k++) {
            float2 av = *(const float2*)&As[buf][k][ty << 1];
            float4 bv = *(const float4*)&Bs[buf][k][tx << 2];
            float bn[4] = {bv.x, bv.y, bv.z, bv.w};
            #pragma unroll
            for (int j = 0; j < 4; j++) {
                acc[0][j] = fmaf(av.x, bn[j], acc[0][j]);
                acc[1][j] = fmaf(av.y, bn[j], acc[1][j]);
            }
        }
        if (has_next) {
            const int nbuf = buf ^ 1;
            As[nbuf][lkA+0][lmA] = an.x; As[nbuf][lkA+1][lmA] = an.y;
            *(float4*)&Bs[nbuf][kb][nb] = sn;
            __syncthreads();
            buf = nbuf;
        }
    }

    #pragma unroll
    for (int i = 0; i < 2; i++) {
        float* orow = out_attn + (row0 + (ty << 1) + i) * DD + col0 + (tx << 2);
        *(float4*)orow = make_float4(acc[i][0], acc[i][1], acc[i][2], acc[i][3]);
    }
}

extern "C" void kernel_launch(void* const* d_in, const int* in_sizes, int n_in,
                              void* d_out, int out_size)
{
    const float* seq  = (const float*)d_in[0];
    const float* mask = (const float*)d_in[1];
    const float* W1   = (const float*)d_in[2];
    const float* W2   = (const float*)d_in[3];
    const float* v    = (const float*)d_in[4];
    float* out_attn = (float*)d_out;                    // [B,S,D]
    float* out_w    = (float*)d_out + BB * SS * DD;     // [B,S,S]

    dim3 g1(PP / 64, (BB * SS) / 32, 2);
    proj_kernel<<<g1, 256>>>(seq, W1, W2);
    score_kernel<<<(BB * SS) / TI, 512>>>(mask, v, out_w);
    dim3 g3(DD / 64, (BB * SS) / 32);
    av_kernel<<<g3, 256>>>(out_w, seq, out_attn);
}

// round 10
// speedup vs baseline: 1.2939x; 1.2939x over previous
#include <cuda_runtime.h>
#include <cstdint>

#define BB 4
#define SS 256
#define DD 512
#define PP 256
#define TI 4
#define PH (PP/2)

// Scratch (device globals — no allocation allowed)
__device__ float g_pq [BB*SS*PP];   // [b][i][p]
__device__ float g_pkT[BB*PP*SS];   // [b][p][j]

__device__ __forceinline__ float fast_tanh(float x) {
    float y; asm("tanh.approx.f32 %0, %1;" : "=f"(y) : "f"(x)); return y;
}

// ---- tf32 helpers -----------------------------------------------------------
__device__ __forceinline__ void split_tf32(float x, uint32_t &hi, uint32_t &lo) {
    asm("cvt.rna.tf32.f32 %0, %1;" : "=r"(hi) : "f"(x));
    float l = x - __uint_as_float(hi);
    asm("cvt.rna.tf32.f32 %0, %1;" : "=r"(lo) : "f"(l));
}
__device__ __forceinline__ void mma_tf32(float* d, const uint32_t* a, const uint32_t* b) {
    asm("mma.sync.aligned.m16n8k8.row.col.f32.tf32.tf32.f32 "
        "{%0,%1,%2,%3},{%4,%5,%6,%7},{%8,%9},{%0,%1,%2,%3};"
        : "+f"(d[0]), "+f"(d[1]), "+f"(d[2]), "+f"(d[3])
        : "r"(a[0]), "r"(a[1]), "r"(a[2]), "r"(a[3]), "r"(b[0]), "r"(b[1]));
}

// ---------------------------------------------------------------------------
// Phase 1 (tensor cores, 3xTF32): pq = seq @ W2^T; pk = seq @ W1^T (transposed).
// 64x64 tile, K-chunk 16, 256 thr (8 warps: 2m x 4n), double-buffered smem.
// Warp = 32(m) x 16(n) = 2x2 m16n8k8 tiles. grid (4,16,2) = 128 CTAs.
// ---------------------------------------------------------------------------
__global__ __launch_bounds__(256, 2) void proj_kernel(
    const float* __restrict__ seq,
    const float* __restrict__ W1,
    const float* __restrict__ W2)
{
    __shared__ float As[2][16][68];   // [buf][k][m]
    __shared__ float Bs[2][16][68];   // [buf][k][n]  (n = p col)
    const float* Wm = blockIdx.z ? W1 : W2;
    const int row0 = blockIdx.y * 64;
    const int col0 = blockIdx.x * 64;
    const int tid = threadIdx.x;
    const int lm = tid >> 2;            // 0..63
    const int lk = (tid & 3) << 2;      // 0,4,8,12

    const int wid = tid >> 5, lane = tid & 31;
    const int wm = (wid & 1) * 32;      // warp m offset
    const int wn = (wid >> 1) * 16;     // warp n offset
    const int g  = lane >> 2;           // groupID
    const int tg = lane & 3;            // threadID_in_group

    const float* ap = seq + (row0 + lm) * DD + lk;
    const float* wp = Wm  + (col0 + lm) * DD + lk;

    {   // prologue chunk 0
        float4 a = *(const float4*)ap;
        float4 w = *(const float4*)wp;
        As[0][lk+0][lm] = a.x; As[0][lk+1][lm] = a.y; As[0][lk+2][lm] = a.z; As[0][lk+3][lm] = a.w;
        Bs[0][lk+0][lm] = w.x; Bs[0][lk+1][lm] = w.y; Bs[0][lk+2][lm] = w.z; Bs[0][lk+3][lm] = w.w;
    }
    __syncthreads();

    float d[2][2][4] = {};
    int buf = 0;

    for (int k0 = 0; k0 < DD; k0 += 16) {
        float4 an, wn4;
        const bool has_next = (k0 + 16) < DD;
        if (has_next) {
            an  = *(const float4*)(ap + k0 + 16);
            wn4 = *(const float4*)(wp + k0 + 16);
        }
        #pragma unroll
        for (int kk = 0; kk < 16; kk += 8) {
            uint32_t ahi[2][4], alo[2][4], bhi[2][2], blo[2][2];
            #pragma unroll
            for (int tm = 0; tm < 2; tm++) {
                const int r0 = wm + tm * 16 + g;
                float f0 = As[buf][kk+tg  ][r0];
                float f1 = As[buf][kk+tg  ][r0+8];
                float f2 = As[buf][kk+tg+4][r0];
                float f3 = As[buf][kk+tg+4][r0+8];
                split_tf32(f0, ahi[tm][0], alo[tm][0]);
                split_tf32(f1, ahi[tm][1], alo[tm][1]);
                split_tf32(f2, ahi[tm][2], alo[tm][2]);
                split_tf32(f3, ahi[tm][3], alo[tm][3]);
            }
            #pragma unroll
            for (int tn = 0; tn < 2; tn++) {
                const int n = wn + tn * 8 + g;
                float f0 = Bs[buf][kk+tg  ][n];
                float f1 = Bs[buf][kk+tg+4][n];
                split_tf32(f0, bhi[tn][0], blo[tn][0]);
                split_tf32(f1, bhi[tn][1], blo[tn][1]);
            }
            #pragma unroll
            for (int tm = 0; tm < 2; tm++)
                #pragma unroll
                for (int tn = 0; tn < 2; tn++) {
                    mma_tf32(d[tm][tn], ahi[tm], bhi[tn]);
                    mma_tf32(d[tm][tn], ahi[tm], blo[tn]);
                    mma_tf32(d[tm][tn], alo[tm], bhi[tn]);
                }
        }
        if (has_next) {
            const int nb = buf ^ 1;
            As[nb][lk+0][lm] = an.x;  As[nb][lk+1][lm] = an.y;  As[nb][lk+2][lm] = an.z;  As[nb][lk+3][lm] = an.w;
            Bs[nb][lk+0][lm] = wn4.x; Bs[nb][lk+1][lm] = wn4.y; Bs[nb][lk+2][lm] = wn4.z; Bs[nb][lk+3][lm] = wn4.w;
            __syncthreads();
            buf = nb;
        }
    }

    // epilogue: c0:(r, c) c1:(r, c+1) c2:(r+8, c) c3:(r+8, c+1)
    const int bofs = (row0 >> 8) * PP;
    #pragma unroll
    for (int tm = 0; tm < 2; tm++) {
        const int r = row0 + wm + tm * 16 + g;
        #pragma unroll
        for (int tn = 0; tn < 2; tn++) {
            const int c = col0 + wn + tn * 8 + 2 * tg;
            if (blockIdx.z == 0) {
                *(float2*)&g_pq[ r      * PP + c] = make_float2(d[tm][tn][0], d[tm][tn][1]);
                *(float2*)&g_pq[(r + 8) * PP + c] = make_float2(d[tm][tn][2], d[tm][tn][3]);
            } else {
                const int jj = r & 255;
                g_pkT[(bofs + c    ) * SS + jj    ] = d[tm][tn][0];
                g_pkT[(bofs + c + 1) * SS + jj    ] = d[tm][tn][1];
                g_pkT[(bofs + c    ) * SS + jj + 8] = d[tm][tn][2];
                g_pkT[(bofs + c + 1) * SS + jj + 8] = d[tm][tn][3];
            }
        }
    }
}

// ---------------------------------------------------------------------------
// Phase 2 (fused): scores (p-split across block halves) + softmax.
// Block = 512 thr: half h reduces p in [h*128, h*128+128); partials meet in
// smem; warps 0..3 softmax + write weights. grid = 256 blocks.
// ---------------------------------------------------------------------------
__global__ __launch_bounds__(512) void score_kernel(
    const float* __restrict__ mask,
    const float* __restrict__ v,
    float* __restrict__ out_w)
{
    __shared__ float pq_s[2][TI][PH];
    __shared__ float v_s[2][PH];
    __shared__ float sp_s[2][TI][SS];

    const int blk = blockIdx.x;
    const int b  = blk >> 6;
    const int i0 = (blk & 63) * TI;
    const int tid = threadIdx.x;
    const int h = tid >> 8;
    const int t = tid & 255;
    const int pbase = h * PH;

    if (t < PH) {
        v_s[h][t] = v[pbase + t];
        #pragma unroll
        for (int ii = 0; ii < TI; ii++)
            pq_s[h][ii][t] = g_pq[(b * SS + i0 + ii) * PP + pbase + t];
    }
    __syncthreads();

    float acc[TI];
    #pragma unroll
    for (int ii = 0; ii < TI; ii++) acc[ii] = 0.f;

    const float* pkp = g_pkT + (b * PP + pbase) * SS + t;
    #pragma unroll 4
    for (int p = 0; p < PH; p++) {
        float pk = pkp[p * SS];
        float vv = v_s[h][p];
        #pragma unroll
        for (int ii = 0; ii < TI; ii++)
            acc[ii] = fmaf(vv, fast_tanh(pq_s[h][ii][p] + pk), acc[ii]);
    }
    #pragma unroll
    for (int ii = 0; ii < TI; ii++)
        sp_s[h][ii][t] = acc[ii];
    __syncthreads();

    if (tid < 128) {
        const int wrp = tid >> 5, lane = tid & 31;
        const float* mrow = mask + b * SS;
        float vals[8];
        float m = -3.4e38f;
        #pragma unroll
        for (int k = 0; k < 8; k++) {
            const int j = lane + 32 * k;
            float s = sp_s[0][wrp][j] + sp_s[1][wrp][j];
            s = (mrow[j] > 0.f) ? s : -1e9f;
            vals[k] = s;
            m = fmaxf(m, s);
        }
        #pragma unroll
        for (int o = 16; o > 0; o >>= 1) m = fmaxf(m, __shfl_xor_sync(0xffffffffu, m, o));
        float sum = 0.f;
        #pragma unroll
        for (int k = 0; k < 8; k++) { vals[k] = __expf(vals[k] - m); sum += vals[k]; }
        #pragma unroll
        for (int o = 16; o > 0; o >>= 1) sum += __shfl_xor_sync(0xffffffffu, sum, o);
        const float qm  = mrow[i0 + wrp];
        const float inv = qm / sum;
        float* orow = out_w + (b * SS + i0 + wrp) * SS;
        #pragma unroll
        for (int k = 0; k < 8; k++)
            orow[lane + 32 * k] = vals[k] * inv;
    }
}

// ---------------------------------------------------------------------------
// Phase 3 (tensor cores, 3xTF32): attn = weights @ seq.
// 64x64 tile, K=256, same warp layout as proj. grid (8,16) = 128 CTAs.
// ---------------------------------------------------------------------------
__global__ __launch_bounds__(256, 2) void av_kernel(
    const float* __restrict__ w,      // [B*S, S]
    const float* __restrict__ seq,    // [B, S, D]
    float* __restrict__ out_attn)     // [B*S, D]
{
    __shared__ float As[2][16][68];   // [buf][k][m]  (weights)
    __shared__ float Bs[2][16][68];   // [buf][k][n]  (seq)
    const int row0 = blockIdx.y * 64;
    const int col0 = blockIdx.x * 64;
    const int b = row0 >> 8;
    const int tid = threadIdx.x;
    const int lm = tid >> 2;
    const int lk = (tid & 3) << 2;
    const int kb = tid >> 4;            // 0..15
    const int nbc = (tid & 15) << 2;    // 0..60

    const int wid = tid >> 5, lane = tid & 31;
    const int wm = (wid & 1) * 32;
    const int wn = (wid >> 1) * 16;
    const int g  = lane >> 2;
    const int tg = lane & 3;

    const float* ap = w + (row0 + lm) * SS + lk;
    const float* sp = seq + b * SS * DD + kb * DD + col0 + nbc;

    {
        float4 a = *(const float4*)ap;
        float4 s = *(const float4*)sp;
        As[0][lk+0][lm] = a.x; As[0][lk+1][lm] = a.y; As[0][lk+2][lm] = a.z; As[0][lk+3][lm] = a.w;
        *(float4*)&Bs[0][kb][nbc] = s;
    }
    __syncthreads();

    float d[2][2][4] = {};
    int buf = 0;

    for (int k0 = 0; k0 < SS; k0 += 16) {
        float4 an, sn;
        const bool has_next = (k0 + 16) < SS;
        if (has_next) {
            an = *(const float4*)(ap + k0 + 16);
            sn = *(const float4*)(sp + (k0 + 16) * DD);
        }
        #pragma unroll
        for (int kk = 0; kk < 16; kk += 8) {
            uint32_t ahi[2][4], alo[2][4], bhi[2][2], blo[2][2];
            #pragma unroll
            for (int tm = 0; tm < 2; tm++) {
                const int r0 = wm + tm * 16 + g;
                float f0 = As[buf][kk+tg  ][r0];
                float f1 = As[buf][kk+tg  ][r0+8];
                float f2 = As[buf][kk+tg+4][r0];
                float f3 = As[buf][kk+tg+4][r0+8];
                split_tf32(f0, ahi[tm][0], alo[tm][0]);
                split_tf32(f1, ahi[tm][1], alo[tm][1]);
                split_tf32(f2, ahi[tm][2], alo[tm][2]);
                split_tf32(f3, ahi[tm][3], alo[tm][3]);
            }
            #pragma unroll
            for (int tn = 0; tn < 2; tn++) {
                const int n = wn + tn * 8 + g;
                float f0 = Bs[buf][kk+tg  ][n];
                float f1 = Bs[buf][kk+tg+4][n];
                split_tf32(f0, bhi[tn][0], blo[tn][0]);
                split_tf32(f1, bhi[tn][1], blo[tn][1]);
            }
            #pragma unroll
            for (int tm = 0; tm < 2; tm++)
                #pragma unroll
                for (int tn = 0; tn < 2; tn++) {
                    mma_tf32(d[tm][tn], ahi[tm], bhi[tn]);
                    mma_tf32(d[tm][tn], ahi[tm], blo[tn]);
                    mma_tf32(d[tm][tn], alo[tm], bhi[tn]);
                }
        }
        if (has_next) {
            const int nb = buf ^ 1;
            As[nb][lk+0][lm] = an.x; As[nb][lk+1][lm] = an.y; As[nb][lk+2][lm] = an.z; As[nb][lk+3][lm] = an.w;
            *(float4*)&Bs[nb][kb][nbc] = sn;
            __syncthreads();
            buf = nb;
        }
    }

    #pragma unroll
    for (int tm = 0; tm < 2; tm++) {
        const int r = row0 + wm + tm * 16 + g;
        #pragma unroll
        for (int tn = 0; tn < 2; tn++) {
            const int c = col0 + wn + tn * 8 + 2 * tg;
            *(float2*)&out_attn[ r      * DD + c] = make_float2(d[tm][tn][0], d[tm][tn][1]);
            *(float2*)&out_attn[(r + 8) * DD + c] = make_float2(d[tm][tn][2], d[tm][tn][3]);
        }
    }
}

extern "C" void kernel_launch(void* const* d_in, const int* in_sizes, int n_in,
                              void* d_out, int out_size)
{
    const float* seq  = (const float*)d_in[0];
    const float* mask = (const float*)d_in[1];
    const float* W1   = (const float*)d_in[2];
    const float* W2   = (const float*)d_in[3];
    const float* v    = (const float*)d_in[4];
    float* out_attn = (float*)d_out;                    // [B,S,D]
    float* out_w    = (float*)d_out + BB * SS * DD;     // [B,S,S]

    dim3 g1(PP / 64, (BB * SS) / 64, 2);
    proj_kernel<<<g1, 256>>>(seq, W1, W2);
    score_kernel<<<(BB * SS) / TI, 512>>>(mask, v, out_w);
    dim3 g3(DD / 64, (BB * SS) / 64);
    av_kernel<<<g3, 256>>>(out_w, seq, out_attn);
}